// round 10
// baseline (speedup 1.0000x reference)
#include <cuda_runtime.h>
#include <math.h>

#define BB 8
#define C 128
#define DL 512
#define R 32
#define VOL (R*R*R)   // 32768

// ---------------- scratch (static device arrays; no allocs) ----------------
__device__ float g_h1[(size_t)BB*C*VOL];     // 134 MB intermediate h1
__device__ float g_s1[BB*C], g_s2[BB*C], g_sv[BB*C];
__device__ float g_sig1[BB*C], g_sig2[BB*C];
__device__ float g_wsq1[C*C], g_wsq2[C*C];
__device__ float g_coefv[BB*C];

// constants
#define C_LIN     0.04419417382415922f   // 1/sqrt(512)
#define IN_SCALE  0.017010345464317122f  // 1/sqrt(128*27)
#define SC2       (1.0f/3456.0f)         // (1/sqrt(3456))^2
#define SCALEV    0.08838834764831845f   // 1/sqrt(128)

// packed fp32x2 FMA: d = a*b + d  (Blackwell FFMA2 — 2x fp32 throughput)
__device__ __forceinline__ void ffma2(float2& d, const float2 a, const float2 b) {
    unsigned long long ua, ub, ud;
    memcpy(&ua, &a, 8); memcpy(&ub, &b, 8); memcpy(&ud, &d, 8);
    asm("fma.rn.f32x2 %0, %1, %2, %0;" : "+l"(ud) : "l"(ua), "l"(ub));
    memcpy(&d, &ud, 8);
}

// ---------------- tiny prep kernels ----------------
__global__ void k_styles(const float* __restrict__ wlat,
                         const float* __restrict__ W1, const float* __restrict__ b1,
                         const float* __restrict__ W2, const float* __restrict__ b2,
                         const float* __restrict__ Wv, const float* __restrict__ bv) {
    int b = blockIdx.x, o = threadIdx.x;
    __shared__ float wl[DL];
    for (int d = o; d < DL; d += C) wl[d] = wlat[b*DL + d];
    __syncthreads();
    float a1 = 0.f, a2 = 0.f, av = 0.f;
    const float* w1r = W1 + o*DL;
    const float* w2r = W2 + o*DL;
    const float* wvr = Wv + o*DL;
    #pragma unroll 8
    for (int d = 0; d < DL; d++) {
        float l = wl[d];
        a1 += l * w1r[d];
        a2 += l * w2r[d];
        av += l * wvr[d];
    }
    g_s1[b*C + o] = a1 * C_LIN + b1[o];
    g_s2[b*C + o] = a2 * C_LIN + b2[o];
    g_sv[b*C + o] = av * C_LIN + bv[o];
}

// full 27-tap squared sums: wsq[o,c] = sum_k w[o,c,k]^2
__global__ void k_wsq(const float* __restrict__ cw1, const float* __restrict__ cw2) {
    int o = blockIdx.x, c = threadIdx.x;
    const float* w = (blockIdx.y ? cw2 : cw1) + (o*C + c) * 27;
    float s = 0.f;
    #pragma unroll
    for (int k = 0; k < 27; k++) { float v = w[k]; s += v * v; }
    (blockIdx.y ? g_wsq2 : g_wsq1)[o*C + c] = s;
}

// sig[b,o] = rsqrt(scale^2 * sum_c s[b,c]^2 * wsq[o,c] + eps)
__global__ void k_sig(const float* __restrict__ cwv) {
    int b = blockIdx.x, t = threadIdx.x;
    __shared__ float s1q[C], s2q[C];
    float s1v = g_s1[b*C + t], s2v = g_s2[b*C + t];
    s1q[t] = s1v * s1v;
    s2q[t] = s2v * s2v;
    g_coefv[b*C + t] = g_sv[b*C + t] * SCALEV * cwv[t];
    __syncthreads();
    float a1 = 0.f, a2 = 0.f;
    #pragma unroll 4
    for (int c = 0; c < C; c++) {
        a1 += s1q[c] * g_wsq1[t*C + c];
        a2 += s2q[c] * g_wsq2[t*C + c];
    }
    g_sig1[b*C + t] = rsqrtf(SC2 * a1 + 1e-8f);
    g_sig2[b*C + t] = rsqrtf(SC2 * a2 + 1e-8f);
}

// ---------------- 3x3x3 modulated conv, fp32x2 packed ----------------
// block: 256 threads; tile = 8x8x8 spatial x 16 out-channels.
// thread: 4 out-channels x 8 x-points (4 float2 pairs) via FFMA2.
template<int PASS>
__global__ void __launch_bounds__(256)
k_conv(const float* __restrict__ in, const float* __restrict__ wt,
       const float* __restrict__ noise, const float* __restrict__ sn,
       const float* __restrict__ bias, float* __restrict__ out) {
    __shared__ __align__(8) float xs[1000];   // 10x10x10 halo tile
    __shared__ float2 ws2[16*27];             // weights pre-duplicated (w,w)

    const int b  = blockIdx.z;
    const int ot = blockIdx.y;                 // 0..7 (16 o each)
    const int sp = blockIdx.x;                 // 0..63
    const int tx = (sp & 3) * 8;
    const int ty = ((sp >> 2) & 3) * 8;
    const int tz = (sp >> 4) * 8;
    const int tid = threadIdx.x;
    const int yz = tid & 63;
    const int y  = yz & 7, z = yz >> 3;
    const int og = tid >> 6;                   // 0..3

    const float* style = (PASS == 1) ? g_s1   : g_s2;
    const float* sig   = (PASS == 1) ? g_sig1 : g_sig2;

    float2 acc[4][4];                          // [oo][pair]: pair j = points 2j,2j+1
    #pragma unroll
    for (int oo = 0; oo < 4; oo++)
        #pragma unroll
        for (int j = 0; j < 4; j++) acc[oo][j] = make_float2(0.f, 0.f);

    for (int c = 0; c < C; c++) {
        const float m = IN_SCALE * style[b*C + c];
        const float* inc = in + ((size_t)(b*C + c)) * VOL;
        __syncthreads();
        // load 10^3 halo tile, zero-padded, pre-modulated
        for (int idx = tid; idx < 1000; idx += 256) {
            int lz = idx / 100;
            int rm = idx - lz * 100;
            int ly = rm / 10;
            int lx = rm - ly * 10;
            int gz = tz + lz - 1, gy = ty + ly - 1, gx = tx + lx - 1;
            float v = 0.f;
            if ((unsigned)gz < 32u && (unsigned)gy < 32u && (unsigned)gx < 32u)
                v = inc[(gz*32 + gy)*32 + gx] * m;
            xs[idx] = v;
        }
        // load 16x27 weights, duplicated into float2 for packed broadcast
        for (int idx = tid; idx < 432; idx += 256) {
            float w = wt[((ot*16 + idx/27) * C + c) * 27 + (idx % 27)];
            ws2[idx] = make_float2(w, w);
        }
        __syncthreads();

        #pragma unroll
        for (int kz = 0; kz < 3; kz++)
        #pragma unroll
        for (int ky = 0; ky < 3; ky++) {
            const int base = ((z + kz)*10 + (y + ky)) * 10;   // always even
            const float2* xp = reinterpret_cast<const float2*>(&xs[base]);
            float2 pA[5];
            #pragma unroll
            for (int i = 0; i < 5; i++) pA[i] = xp[i];
            float2 pB[4];
            #pragma unroll
            for (int i = 0; i < 4; i++) pB[i] = make_float2(pA[i].y, pA[i+1].x);

            const int tapb = (kz*3 + ky)*3;
            #pragma unroll
            for (int oo = 0; oo < 4; oo++) {
                const float2* wrow = &ws2[(og*4 + oo)*27 + tapb];
                const float2 w0 = wrow[0], w1 = wrow[1], w2 = wrow[2];
                #pragma unroll
                for (int j = 0; j < 4; j++) ffma2(acc[oo][j], pA[j],   w0);
                #pragma unroll
                for (int j = 0; j < 4; j++) ffma2(acc[oo][j], pB[j],   w1);
                #pragma unroll
                for (int j = 0; j < 4; j++) ffma2(acc[oo][j], pA[j+1], w2);
            }
        }
    }

    // epilogue: demod + noise + bias + leaky relu
    const float snv = sn[0];
    const int gz = tz + z, gy = ty + y;
    const int spbase = (gz*32 + gy)*32 + tx;
    float nz[8];
    #pragma unroll
    for (int i = 0; i < 8; i++) nz[i] = noise[b*VOL + spbase + i];
    #pragma unroll
    for (int oo = 0; oo < 4; oo++) {
        const int o = ot*16 + og*4 + oo;
        const float sg = sig[b*C + o];
        const float bi = bias[o];
        float* op = out + ((size_t)(b*C + o)) * VOL + spbase;
        #pragma unroll
        for (int j = 0; j < 4; j++) {
            float v0 = acc[oo][j].x * sg + snv * nz[2*j]   + bi;
            float v1 = acc[oo][j].y * sg + snv * nz[2*j+1] + bi;
            op[2*j]   = (v0 >= 0.f) ? v0 : 0.2f * v0;
            op[2*j+1] = (v1 >= 0.f) ? v1 : 0.2f * v1;
        }
    }
}

// ---------------- to_volume: 1x1x1 conv over channels ----------------
__global__ void k_vol(const float* __restrict__ h2, const float* __restrict__ biasv,
                      float* __restrict__ vol) {
    const int b = blockIdx.y;
    const int p0 = blockIdx.x * 512;
    const int tid = threadIdx.x;
    __shared__ float cf[C];
    if (tid < C) cf[tid] = g_coefv[b*C + tid];
    __syncthreads();
    float a0 = 0.f, a1 = 0.f;
    for (int c = 0; c < C; c++) {
        const float* hp = h2 + ((size_t)(b*C + c)) * VOL + p0;
        const float cv = cf[c];
        a0 += cv * hp[tid];
        a1 += cv * hp[tid + 256];
    }
    const float bv = biasv[0];
    float v0 = a0 + bv, v1 = a1 + bv;
    vol[b*VOL + p0 + tid]       = (v0 >= 0.f) ? v0 : 0.2f * v0;
    vol[b*VOL + p0 + tid + 256] = (v1 >= 0.f) ? v1 : 0.2f * v1;
}

// diagnostic marker (decodable constant)
__global__ void k_mark(float* __restrict__ out, int n, float v) {
    for (int i = blockIdx.x * blockDim.x + threadIdx.x; i < n;
         i += gridDim.x * blockDim.x)
        out[i] = v;
}

// ---------------- launch ----------------
extern "C" void kernel_launch(void* const* d_in, const int* in_sizes, int n_in,
                              void* d_out, int out_size) {
    float* out = (float*)d_out;

    static const int sig[18] = {
        33554432, 4096, 262144, 262144,        // x, w_lat, noise1, noise2
        65536, 128, 442368, 1, 128,            // W1, b1, cw1, sn1, bias1
        65536, 128, 442368, 1, 128,            // W2, b2, cw2, sn2, bias2
        65536, 128, 128, 1                     // Wv, bv, cwv, biasv
    };
    if (n_in != 18) {
        int k = (n_in < 16) ? 1 : (n_in - 15); if (k > 8) k = 8;
        k_mark<<<256, 256>>>(out, out_size, (float)(1 << (2 * k)));
        return;
    }
    for (int i = 0; i < 18; i++) {
        if (in_sizes[i] != sig[i]) {
            k_mark<<<256, 256>>>(out, out_size, 1.0e6f + (float)in_sizes[i]);
            return;
        }
    }

    const float* x      = (const float*)d_in[0];
    const float* wlat   = (const float*)d_in[1];
    const float* noise1 = (const float*)d_in[2];
    const float* noise2 = (const float*)d_in[3];
    const float* W1     = (const float*)d_in[4];
    const float* b1     = (const float*)d_in[5];
    const float* cw1    = (const float*)d_in[6];
    const float* sn1    = (const float*)d_in[7];
    const float* bias1  = (const float*)d_in[8];
    const float* W2     = (const float*)d_in[9];
    const float* b2     = (const float*)d_in[10];
    const float* cw2    = (const float*)d_in[11];
    const float* sn2    = (const float*)d_in[12];
    const float* bias2  = (const float*)d_in[13];
    const float* Wv     = (const float*)d_in[14];
    const float* bv     = (const float*)d_in[15];
    const float* cwv    = (const float*)d_in[16];
    const float* biasv  = (const float*)d_in[17];

    float* h1 = nullptr;
    cudaGetSymbolAddress((void**)&h1, g_h1);

    k_styles<<<BB, C>>>(wlat, W1, b1, W2, b2, Wv, bv);
    k_wsq<<<dim3(C, 2), C>>>(cw1, cw2);
    k_sig<<<BB, C>>>(cwv);
    k_conv<1><<<dim3(64, 8, BB), 256>>>(x,  cw1, noise1, sn1, bias1, h1);
    k_conv<2><<<dim3(64, 8, BB), 256>>>(h1, cw2, noise2, sn2, bias2, out);
    if (out_size >= BB*C*VOL + BB*VOL)
        k_vol<<<dim3(64, BB), 256>>>(out, biasv, out + (size_t)BB*C*VOL);
}

// round 11
// speedup vs baseline: 1.1087x; 1.1087x over previous
#include <cuda_runtime.h>
#include <math.h>

#define BB 8
#define C 128
#define DL 512
#define R 32
#define VOL (R*R*R)   // 32768

typedef unsigned long long u64;

// ---------------- scratch (static device arrays; no allocs) ----------------
__device__ float g_h1[(size_t)BB*C*VOL];     // 134 MB intermediate h1
__device__ float g_s1[BB*C], g_s2[BB*C], g_sv[BB*C];
__device__ float g_sig1[BB*C], g_sig2[BB*C];
__device__ float g_wsq1[C*C], g_wsq2[C*C];
__device__ float g_coefv[BB*C];

// constants
#define C_LIN     0.04419417382415922f   // 1/sqrt(512)
#define IN_SCALE  0.017010345464317122f  // 1/sqrt(128*27)
#define SC2       (1.0f/3456.0f)         // (1/sqrt(3456))^2
#define SCALEV    0.08838834764831845f   // 1/sqrt(128)

// packed fp32x2 FMA on raw u64 pairs: d = a*b + d  (single SASS FFMA2, no MOVs)
__device__ __forceinline__ void ffma2u(u64& d, const u64 a, const u64 b) {
    asm("fma.rn.f32x2 %0, %1, %2, %0;" : "+l"(d) : "l"(a), "l"(b));
}

// ---------------- tiny prep kernels ----------------
__global__ void k_styles(const float* __restrict__ wlat,
                         const float* __restrict__ W1, const float* __restrict__ b1,
                         const float* __restrict__ W2, const float* __restrict__ b2,
                         const float* __restrict__ Wv, const float* __restrict__ bv) {
    int b = blockIdx.x, o = threadIdx.x;
    __shared__ float wl[DL];
    for (int d = o; d < DL; d += C) wl[d] = wlat[b*DL + d];
    __syncthreads();
    float a1 = 0.f, a2 = 0.f, av = 0.f;
    const float* w1r = W1 + o*DL;
    const float* w2r = W2 + o*DL;
    const float* wvr = Wv + o*DL;
    #pragma unroll 8
    for (int d = 0; d < DL; d++) {
        float l = wl[d];
        a1 += l * w1r[d];
        a2 += l * w2r[d];
        av += l * wvr[d];
    }
    g_s1[b*C + o] = a1 * C_LIN + b1[o];
    g_s2[b*C + o] = a2 * C_LIN + b2[o];
    g_sv[b*C + o] = av * C_LIN + bv[o];
}

// full 27-tap squared sums: wsq[o,c] = sum_k w[o,c,k]^2
__global__ void k_wsq(const float* __restrict__ cw1, const float* __restrict__ cw2) {
    int o = blockIdx.x, c = threadIdx.x;
    const float* w = (blockIdx.y ? cw2 : cw1) + (o*C + c) * 27;
    float s = 0.f;
    #pragma unroll
    for (int k = 0; k < 27; k++) { float v = w[k]; s += v * v; }
    (blockIdx.y ? g_wsq2 : g_wsq1)[o*C + c] = s;
}

// sig[b,o] = rsqrt(scale^2 * sum_c s[b,c]^2 * wsq[o,c] + eps)
__global__ void k_sig(const float* __restrict__ cwv) {
    int b = blockIdx.x, t = threadIdx.x;
    __shared__ float s1q[C], s2q[C];
    float s1v = g_s1[b*C + t], s2v = g_s2[b*C + t];
    s1q[t] = s1v * s1v;
    s2q[t] = s2v * s2v;
    g_coefv[b*C + t] = g_sv[b*C + t] * SCALEV * cwv[t];
    __syncthreads();
    float a1 = 0.f, a2 = 0.f;
    #pragma unroll 4
    for (int c = 0; c < C; c++) {
        a1 += s1q[c] * g_wsq1[t*C + c];
        a2 += s2q[c] * g_wsq2[t*C + c];
    }
    g_sig1[b*C + t] = rsqrtf(SC2 * a1 + 1e-8f);
    g_sig2[b*C + t] = rsqrtf(SC2 * a2 + 1e-8f);
}

// ---------------- 3x3x3 modulated conv, packed FFMA2 (u64 form) ----------------
// block: 256 threads; tile = 8x8x8 spatial x 16 out-channels.
// thread: 4 out-channels x 8 x-points (4 packed pairs).
// xs2 = xs shifted by one element so odd-aligned pairs are plain LDS.64.
template<int PASS>
__global__ void __launch_bounds__(256)
k_conv(const float* __restrict__ in, const float* __restrict__ wt,
       const float* __restrict__ noise, const float* __restrict__ sn,
       const float* __restrict__ bias, float* __restrict__ out) {
    __shared__ __align__(8) float xs[1000];    // halo tile
    __shared__ __align__(8) float xs2[1000];   // xs2[i] = xs[i+1]
    __shared__ u64 wsu[16*27];                 // weights packed (w,w)

    const int b  = blockIdx.z;
    const int ot = blockIdx.y;                 // 0..7 (16 o each)
    const int sp = blockIdx.x;                 // 0..63
    const int tx = (sp & 3) * 8;
    const int ty = ((sp >> 2) & 3) * 8;
    const int tz = (sp >> 4) * 8;
    const int tid = threadIdx.x;
    const int yz = tid & 63;
    const int y  = yz & 7, z = yz >> 3;
    const int og = tid >> 6;                   // 0..3

    const float* style = (PASS == 1) ? g_s1   : g_s2;
    const float* sig   = (PASS == 1) ? g_sig1 : g_sig2;

    u64 acc[4][4];                             // [oo][pair]; (0.f,0.f) == 0ULL
    #pragma unroll
    for (int oo = 0; oo < 4; oo++)
        #pragma unroll
        for (int j = 0; j < 4; j++) acc[oo][j] = 0ULL;

    for (int c = 0; c < C; c++) {
        const float m = IN_SCALE * style[b*C + c];
        const float* inc = in + ((size_t)(b*C + c)) * VOL;
        __syncthreads();
        // load 10^3 halo tile (pre-modulated) + shifted copy
        for (int idx = tid; idx < 1000; idx += 256) {
            int lz = idx / 100;
            int rm = idx - lz * 100;
            int ly = rm / 10;
            int lx = rm - ly * 10;
            int gz = tz + lz - 1, gy = ty + ly - 1, gx = tx + lx - 1;
            float v = 0.f;
            if ((unsigned)gz < 32u && (unsigned)gy < 32u && (unsigned)gx < 32u)
                v = inc[(gz*32 + gy)*32 + gx] * m;
            xs[idx] = v;
            if (idx > 0) xs2[idx - 1] = v;
        }
        // weights packed (w,w) as u64
        for (int idx = tid; idx < 432; idx += 256) {
            unsigned int wb = __float_as_uint(
                wt[((ot*16 + idx/27) * C + c) * 27 + (idx % 27)]);
            wsu[idx] = ((u64)wb << 32) | wb;
        }
        __syncthreads();

        #pragma unroll
        for (int kz = 0; kz < 3; kz++)
        #pragma unroll
        for (int ky = 0; ky < 3; ky++) {
            const int base = ((z + kz)*10 + (y + ky)) * 10;   // always even
            u64 pA[5], pB[4];
            #pragma unroll
            for (int i = 0; i < 5; i++)
                pA[i] = *reinterpret_cast<const u64*>(&xs[base + 2*i]);
            #pragma unroll
            for (int i = 0; i < 4; i++)
                pB[i] = *reinterpret_cast<const u64*>(&xs2[base + 2*i]);

            const int tapb = (kz*3 + ky)*3;
            #pragma unroll
            for (int oo = 0; oo < 4; oo++) {
                const u64* wrow = &wsu[(og*4 + oo)*27 + tapb];
                const u64 w0 = wrow[0], w1 = wrow[1], w2 = wrow[2];
                #pragma unroll
                for (int j = 0; j < 4; j++) ffma2u(acc[oo][j], pA[j],   w0);
                #pragma unroll
                for (int j = 0; j < 4; j++) ffma2u(acc[oo][j], pB[j],   w1);
                #pragma unroll
                for (int j = 0; j < 4; j++) ffma2u(acc[oo][j], pA[j+1], w2);
            }
        }
    }

    // epilogue: demod + noise + bias + leaky relu
    const float snv = sn[0];
    const int gz = tz + z, gy = ty + y;
    const int spbase = (gz*32 + gy)*32 + tx;
    float nz[8];
    #pragma unroll
    for (int i = 0; i < 8; i++) nz[i] = noise[b*VOL + spbase + i];
    #pragma unroll
    for (int oo = 0; oo < 4; oo++) {
        const int o = ot*16 + og*4 + oo;
        const float sg = sig[b*C + o];
        const float bi = bias[o];
        float* op = out + ((size_t)(b*C + o)) * VOL + spbase;
        #pragma unroll
        for (int j = 0; j < 4; j++) {
            float lo = __uint_as_float((unsigned)(acc[oo][j] & 0xffffffffULL));
            float hi = __uint_as_float((unsigned)(acc[oo][j] >> 32));
            float v0 = lo * sg + snv * nz[2*j]   + bi;
            float v1 = hi * sg + snv * nz[2*j+1] + bi;
            op[2*j]   = (v0 >= 0.f) ? v0 : 0.2f * v0;
            op[2*j+1] = (v1 >= 0.f) ? v1 : 0.2f * v1;
        }
    }
}

// ---------------- to_volume: 1x1x1 conv over channels ----------------
__global__ void k_vol(const float* __restrict__ h2, const float* __restrict__ biasv,
                      float* __restrict__ vol) {
    const int b = blockIdx.y;
    const int p0 = blockIdx.x * 512;
    const int tid = threadIdx.x;
    __shared__ float cf[C];
    if (tid < C) cf[tid] = g_coefv[b*C + tid];
    __syncthreads();
    float a0 = 0.f, a1 = 0.f;
    for (int c = 0; c < C; c++) {
        const float* hp = h2 + ((size_t)(b*C + c)) * VOL + p0;
        const float cv = cf[c];
        a0 += cv * hp[tid];
        a1 += cv * hp[tid + 256];
    }
    const float bv = biasv[0];
    float v0 = a0 + bv, v1 = a1 + bv;
    vol[b*VOL + p0 + tid]       = (v0 >= 0.f) ? v0 : 0.2f * v0;
    vol[b*VOL + p0 + tid + 256] = (v1 >= 0.f) ? v1 : 0.2f * v1;
}

// diagnostic marker (decodable constant)
__global__ void k_mark(float* __restrict__ out, int n, float v) {
    for (int i = blockIdx.x * blockDim.x + threadIdx.x; i < n;
         i += gridDim.x * blockDim.x)
        out[i] = v;
}

// ---------------- launch ----------------
extern "C" void kernel_launch(void* const* d_in, const int* in_sizes, int n_in,
                              void* d_out, int out_size) {
    float* out = (float*)d_out;

    static const int sig[18] = {
        33554432, 4096, 262144, 262144,        // x, w_lat, noise1, noise2
        65536, 128, 442368, 1, 128,            // W1, b1, cw1, sn1, bias1
        65536, 128, 442368, 1, 128,            // W2, b2, cw2, sn2, bias2
        65536, 128, 128, 1                     // Wv, bv, cwv, biasv
    };
    if (n_in != 18) {
        int k = (n_in < 16) ? 1 : (n_in - 15); if (k > 8) k = 8;
        k_mark<<<256, 256>>>(out, out_size, (float)(1 << (2 * k)));
        return;
    }
    for (int i = 0; i < 18; i++) {
        if (in_sizes[i] != sig[i]) {
            k_mark<<<256, 256>>>(out, out_size, 1.0e6f + (float)in_sizes[i]);
            return;
        }
    }

    const float* x      = (const float*)d_in[0];
    const float* wlat   = (const float*)d_in[1];
    const float* noise1 = (const float*)d_in[2];
    const float* noise2 = (const float*)d_in[3];
    const float* W1     = (const float*)d_in[4];
    const float* b1     = (const float*)d_in[5];
    const float* cw1    = (const float*)d_in[6];
    const float* sn1    = (const float*)d_in[7];
    const float* bias1  = (const float*)d_in[8];
    const float* W2     = (const float*)d_in[9];
    const float* b2     = (const float*)d_in[10];
    const float* cw2    = (const float*)d_in[11];
    const float* sn2    = (const float*)d_in[12];
    const float* bias2  = (const float*)d_in[13];
    const float* Wv     = (const float*)d_in[14];
    const float* bv     = (const float*)d_in[15];
    const float* cwv    = (const float*)d_in[16];
    const float* biasv  = (const float*)d_in[17];

    float* h1 = nullptr;
    cudaGetSymbolAddress((void**)&h1, g_h1);

    k_styles<<<BB, C>>>(wlat, W1, b1, W2, b2, Wv, bv);
    k_wsq<<<dim3(C, 2), C>>>(cw1, cw2);
    k_sig<<<BB, C>>>(cwv);
    k_conv<1><<<dim3(64, 8, BB), 256>>>(x,  cw1, noise1, sn1, bias1, h1);
    k_conv<2><<<dim3(64, 8, BB), 256>>>(h1, cw2, noise2, sn2, bias2, out);
    if (out_size >= BB*C*VOL + BB*VOL)
        k_vol<<<dim3(64, BB), 256>>>(out, biasv, out + (size_t)BB*C*VOL);
}

// round 13
// speedup vs baseline: 1.1779x; 1.0624x over previous
#include <cuda_runtime.h>
#include <math.h>

#define BB 8
#define C 128
#define DL 512
#define R 32
#define VOL (R*R*R)   // 32768

typedef unsigned long long u64;
typedef unsigned int u32;

// ---------------- scratch (static device arrays; no allocs) ----------------
__device__ float g_h1[(size_t)BB*C*VOL];     // 134 MB intermediate h1
__device__ float g_s1[BB*C], g_s2[BB*C], g_sv[BB*C];
__device__ float g_sig1[BB*C], g_sig2[BB*C];
__device__ float g_wsq1[C*C], g_wsq2[C*C];
__device__ float g_coefv[BB*C];

// constants
#define C_LIN     0.04419417382415922f   // 1/sqrt(512)
#define IN_SCALE  0.017010345464317122f  // 1/sqrt(128*27)
#define SC2       (1.0f/3456.0f)         // (1/sqrt(3456))^2
#define SCALEV    0.08838834764831845f   // 1/sqrt(128)

// packed fp32x2 FMA on raw u64 pairs: d = a*b + d
__device__ __forceinline__ void ffma2u(u64& d, const u64 a, const u64 b) {
    asm("fma.rn.f32x2 %0, %1, %2, %0;" : "+l"(d) : "l"(a), "l"(b));
}
__device__ __forceinline__ u64 pack2(u32 lo, u32 hi) {
    return (u64)lo | ((u64)hi << 32);
}

// ---------------- tiny prep kernels ----------------
__global__ void k_styles(const float* __restrict__ wlat,
                         const float* __restrict__ W1, const float* __restrict__ b1,
                         const float* __restrict__ W2, const float* __restrict__ b2,
                         const float* __restrict__ Wv, const float* __restrict__ bv) {
    int b = blockIdx.x, o = threadIdx.x;
    __shared__ float wl[DL];
    for (int d = o; d < DL; d += C) wl[d] = wlat[b*DL + d];
    __syncthreads();
    float a1 = 0.f, a2 = 0.f, av = 0.f;
    const float* w1r = W1 + o*DL;
    const float* w2r = W2 + o*DL;
    const float* wvr = Wv + o*DL;
    #pragma unroll 8
    for (int d = 0; d < DL; d++) {
        float l = wl[d];
        a1 += l * w1r[d];
        a2 += l * w2r[d];
        av += l * wvr[d];
    }
    g_s1[b*C + o] = a1 * C_LIN + b1[o];
    g_s2[b*C + o] = a2 * C_LIN + b2[o];
    g_sv[b*C + o] = av * C_LIN + bv[o];
}

__global__ void k_wsq(const float* __restrict__ cw1, const float* __restrict__ cw2) {
    int o = blockIdx.x, c = threadIdx.x;
    const float* w = (blockIdx.y ? cw2 : cw1) + (o*C + c) * 27;
    float s = 0.f;
    #pragma unroll
    for (int k = 0; k < 27; k++) { float v = w[k]; s += v * v; }
    (blockIdx.y ? g_wsq2 : g_wsq1)[o*C + c] = s;
}

__global__ void k_sig(const float* __restrict__ cwv) {
    int b = blockIdx.x, t = threadIdx.x;
    __shared__ float s1q[C], s2q[C];
    float s1v = g_s1[b*C + t], s2v = g_s2[b*C + t];
    s1q[t] = s1v * s1v;
    s2q[t] = s2v * s2v;
    g_coefv[b*C + t] = g_sv[b*C + t] * SCALEV * cwv[t];
    __syncthreads();
    float a1 = 0.f, a2 = 0.f;
    #pragma unroll 4
    for (int c = 0; c < C; c++) {
        a1 += s1q[c] * g_wsq1[t*C + c];
        a2 += s2q[c] * g_wsq2[t*C + c];
    }
    g_sig1[b*C + t] = rsqrtf(SC2 * a1 + 1e-8f);
    g_sig2[b*C + t] = rsqrtf(SC2 * a2 + 1e-8f);
}

// ---------------- 3x3x3 modulated conv: FFMA2 + vectorized LDS ----------------
// block: 256 threads; tile 8x8x8 spatial x 16 oo.
// xs rows padded to 12 floats (48B) so rows load as 2x LDS.128 + 1x LDS.64.
// weights in smem as u64 (w,w) laid out [tap][16 oo] -> 4-oo group = LDS.128 x2.
template<int PASS>
__global__ void __launch_bounds__(256)
k_conv(const float* __restrict__ in, const float* __restrict__ wt,
       const float* __restrict__ noise, const float* __restrict__ sn,
       const float* __restrict__ bias, float* __restrict__ out) {
    __shared__ __align__(16) float xs[100*12];   // 10x10 rows x 12-stride
    __shared__ __align__(16) u64  wsu[27*16];    // [tap][oo] packed (w,w)

    const int b  = blockIdx.z;
    const int ot = blockIdx.y;                 // 0..7 (16 o each)
    const int sp = blockIdx.x;                 // 0..63
    const int tx = (sp & 3) * 8;
    const int ty = ((sp >> 2) & 3) * 8;
    const int tz = (sp >> 4) * 8;
    const int tid = threadIdx.x;
    const int yz = tid & 63;
    const int y  = yz & 7, z = yz >> 3;
    const int og = tid >> 6;                   // 0..3

    const float* style = (PASS == 1) ? g_s1   : g_s2;
    const float* sig   = (PASS == 1) ? g_sig1 : g_sig2;

    u64 acc[4][4];                             // [oo][pair]
    #pragma unroll
    for (int oo = 0; oo < 4; oo++)
        #pragma unroll
        for (int j = 0; j < 4; j++) acc[oo][j] = 0ULL;

    for (int c = 0; c < C; c++) {
        const float m = IN_SCALE * style[b*C + c];
        const float* inc = in + ((size_t)(b*C + c)) * VOL;
        __syncthreads();
        // halo tile (pre-modulated), padded row stride 12
        for (int idx = tid; idx < 1000; idx += 256) {
            int lz = idx / 100;
            int rm = idx - lz * 100;
            int ly = rm / 10;
            int lx = rm - ly * 10;
            int gz = tz + lz - 1, gy = ty + ly - 1, gx = tx + lx - 1;
            float v = 0.f;
            if ((unsigned)gz < 32u && (unsigned)gy < 32u && (unsigned)gx < 32u)
                v = inc[(gz*32 + gy)*32 + gx] * m;
            xs[(lz*10 + ly)*12 + lx] = v;
        }
        // weights: wsu[tap*16 + o_local] = (w,w)
        for (int idx = tid; idx < 432; idx += 256) {
            int tap = idx >> 4, o = idx & 15;
            u32 wb = __float_as_uint(wt[((ot*16 + o) * C + c) * 27 + tap]);
            wsu[idx] = pack2(wb, wb);
        }
        __syncthreads();

        #pragma unroll
        for (int kz = 0; kz < 3; kz++)
        #pragma unroll
        for (int ky = 0; ky < 3; ky++) {
            const int base = ((z + kz)*10 + (y + ky)) * 12;   // 48B-aligned
            // vector-load 10 scalars
            float4 v0 = *reinterpret_cast<const float4*>(&xs[base]);
            float4 v1 = *reinterpret_cast<const float4*>(&xs[base + 4]);
            float2 v2 = *reinterpret_cast<const float2*>(&xs[base + 8]);
            u32 r0 = __float_as_uint(v0.x), r1 = __float_as_uint(v0.y);
            u32 r2 = __float_as_uint(v0.z), r3 = __float_as_uint(v0.w);
            u32 r4 = __float_as_uint(v1.x), r5 = __float_as_uint(v1.y);
            u32 r6 = __float_as_uint(v1.z), r7 = __float_as_uint(v1.w);
            u32 r8 = __float_as_uint(v2.x), r9 = __float_as_uint(v2.y);
            u64 pA[5], pB[4];
            pA[0] = pack2(r0, r1); pA[1] = pack2(r2, r3);
            pA[2] = pack2(r4, r5); pA[3] = pack2(r6, r7);
            pA[4] = pack2(r8, r9);
            pB[0] = pack2(r1, r2); pB[1] = pack2(r3, r4);
            pB[2] = pack2(r5, r6); pB[3] = pack2(r7, r8);

            const int tapb = (kz*3 + ky)*3;
            // per kx tap: 4-oo weight group = 2x LDS.128
            #pragma unroll
            for (int kx = 0; kx < 3; kx++) {
                const u64* wrow = &wsu[(tapb + kx)*16 + og*4];
                u64 w0 = wrow[0], w1 = wrow[1], w2 = wrow[2], w3 = wrow[3];
                const u64* px = (kx == 0) ? pA : ((kx == 1) ? pB : (pA + 1));
                #pragma unroll
                for (int j = 0; j < 4; j++) ffma2u(acc[0][j], px[j], w0);
                #pragma unroll
                for (int j = 0; j < 4; j++) ffma2u(acc[1][j], px[j], w1);
                #pragma unroll
                for (int j = 0; j < 4; j++) ffma2u(acc[2][j], px[j], w2);
                #pragma unroll
                for (int j = 0; j < 4; j++) ffma2u(acc[3][j], px[j], w3);
            }
        }
    }

    // epilogue: demod + noise + bias + leaky relu
    const float snv = sn[0];
    const int gz = tz + z, gy = ty + y;
    const int spbase = (gz*32 + gy)*32 + tx;
    float nz[8];
    #pragma unroll
    for (int i = 0; i < 8; i++) nz[i] = noise[b*VOL + spbase + i];
    #pragma unroll
    for (int oo = 0; oo < 4; oo++) {
        const int o = ot*16 + og*4 + oo;
        const float sg = sig[b*C + o];
        const float bi = bias[o];
        float* op = out + ((size_t)(b*C + o)) * VOL + spbase;
        #pragma unroll
        for (int j = 0; j < 4; j++) {
            float lo = __uint_as_float((u32)(acc[oo][j] & 0xffffffffULL));
            float hi = __uint_as_float((u32)(acc[oo][j] >> 32));
            float v0 = lo * sg + snv * nz[2*j]   + bi;
            float v1 = hi * sg + snv * nz[2*j+1] + bi;
            op[2*j]   = (v0 >= 0.f) ? v0 : 0.2f * v0;
            op[2*j+1] = (v1 >= 0.f) ? v1 : 0.2f * v1;
        }
    }
}

// ---------------- to_volume: 1x1x1 conv over channels ----------------
__global__ void k_vol(const float* __restrict__ h2, const float* __restrict__ biasv,
                      float* __restrict__ vol) {
    const int b = blockIdx.y;
    const int p0 = blockIdx.x * 512;
    const int tid = threadIdx.x;
    __shared__ float cf[C];
    if (tid < C) cf[tid] = g_coefv[b*C + tid];
    __syncthreads();
    float a0 = 0.f, a1 = 0.f;
    for (int c = 0; c < C; c++) {
        const float* hp = h2 + ((size_t)(b*C + c)) * VOL + p0;
        const float cv = cf[c];
        a0 += cv * hp[tid];
        a1 += cv * hp[tid + 256];
    }
    const float bv = biasv[0];
    float v0 = a0 + bv, v1 = a1 + bv;
    vol[b*VOL + p0 + tid]       = (v0 >= 0.f) ? v0 : 0.2f * v0;
    vol[b*VOL + p0 + tid + 256] = (v1 >= 0.f) ? v1 : 0.2f * v1;
}

// diagnostic marker
__global__ void k_mark(float* __restrict__ out, int n, float v) {
    for (int i = blockIdx.x * blockDim.x + threadIdx.x; i < n;
         i += gridDim.x * blockDim.x)
        out[i] = v;
}

// ---------------- launch ----------------
extern "C" void kernel_launch(void* const* d_in, const int* in_sizes, int n_in,
                              void* d_out, int out_size) {
    float* out = (float*)d_out;

    static const int sig[18] = {
        33554432, 4096, 262144, 262144,
        65536, 128, 442368, 1, 128,
        65536, 128, 442368, 1, 128,
        65536, 128, 128, 1
    };
    if (n_in != 18) {
        int k = (n_in < 16) ? 1 : (n_in - 15); if (k > 8) k = 8;
        k_mark<<<256, 256>>>(out, out_size, (float)(1 << (2 * k)));
        return;
    }
    for (int i = 0; i < 18; i++) {
        if (in_sizes[i] != sig[i]) {
            k_mark<<<256, 256>>>(out, out_size, 1.0e6f + (float)in_sizes[i]);
            return;
        }
    }

    const float* x      = (const float*)d_in[0];
    const float* wlat   = (const float*)d_in[1];
    const float* noise1 = (const float*)d_in[2];
    const float* noise2 = (const float*)d_in[3];
    const float* W1     = (const float*)d_in[4];
    const float* b1     = (const float*)d_in[5];
    const float* cw1    = (const float*)d_in[6];
    const float* sn1    = (const float*)d_in[7];
    const float* bias1  = (const float*)d_in[8];
    const float* W2     = (const float*)d_in[9];
    const float* b2     = (const float*)d_in[10];
    const float* cw2    = (const float*)d_in[11];
    const float* sn2    = (const float*)d_in[12];
    const float* bias2  = (const float*)d_in[13];
    const float* Wv     = (const float*)d_in[14];
    const float* bv     = (const float*)d_in[15];
    const float* cwv    = (const float*)d_in[16];
    const float* biasv  = (const float*)d_in[17];

    float* h1 = nullptr;
    cudaGetSymbolAddress((void**)&h1, g_h1);

    k_styles<<<BB, C>>>(wlat, W1, b1, W2, b2, Wv, bv);
    k_wsq<<<dim3(C, 2), C>>>(cw1, cw2);
    k_sig<<<BB, C>>>(cwv);
    k_conv<1><<<dim3(64, 8, BB), 256>>>(x,  cw1, noise1, sn1, bias1, h1);
    k_conv<2><<<dim3(64, 8, BB), 256>>>(h1, cw2, noise2, sn2, bias2, out);
    if (out_size >= BB*C*VOL + BB*VOL)
        k_vol<<<dim3(64, BB), 256>>>(out, biasv, out + (size_t)BB*C*VOL);
}

// round 17
// speedup vs baseline: 2.3437x; 1.9897x over previous
#include <cuda_runtime.h>
#include <math.h>

#define BB 8
#define C 128
#define DL 512
#define R 32
#define VOL (R*R*R)   // 32768

typedef unsigned long long u64;
typedef unsigned int u32;

// ---------------- scratch (static device arrays; no allocs) ----------------
__device__ float g_h1[(size_t)BB*C*VOL];       // 134 MB intermediate h1
__device__ float g_wt[2][27*C*C];              // weights [pass][tap][c][o], tf32-rounded
__device__ float g_s1[BB*C], g_s2[BB*C], g_sv[BB*C];
__device__ float g_sig1[BB*C], g_sig2[BB*C];
__device__ float g_wsq1[C*C], g_wsq2[C*C];
__device__ float g_coefv[BB*C];

// constants
#define C_LIN     0.04419417382415922f   // 1/sqrt(512)
#define IN_SCALE  0.017010345464317122f  // 1/sqrt(128*27)
#define SC2       (1.0f/3456.0f)         // (1/sqrt(3456))^2
#define SCALEV    0.08838834764831845f   // 1/sqrt(128)

// smem geometry: tiles [32 k][128 v] with row stride 136 floats (conflict-free)
#define TSTRIDE 136
#define TILE_BYTES (32*TSTRIDE*4)        // 17408
#define BUF_BYTES  (2*TILE_BYTES)        // A+B = 34816
#define M_OFF      (2*BUF_BYTES)         // 69632: 128 style floats
#define CSMEM      (M_OFF + 512)

__device__ __forceinline__ u32 smem_u32(const void* p) {
    u32 a;
    asm("{ .reg .u64 t; cvta.to.shared.u64 t, %1; cvt.u32.u64 %0, t; }" : "=r"(a) : "l"(p));
    return a;
}
__device__ __forceinline__ void sts32(u32 addr, u32 v) {
    asm volatile("st.shared.b32 [%0], %1;" :: "r"(addr), "r"(v) : "memory");
}
__device__ __forceinline__ void sts128(u32 addr, float4 v) {
    asm volatile("st.shared.v4.b32 [%0], {%1,%2,%3,%4};"
        :: "r"(addr), "r"(__float_as_uint(v.x)), "r"(__float_as_uint(v.y)),
           "r"(__float_as_uint(v.z)), "r"(__float_as_uint(v.w)) : "memory");
}
__device__ __forceinline__ u32 lds32(u32 addr) {
    u32 v;
    asm volatile("ld.shared.b32 %0, [%1];" : "=r"(v) : "r"(addr));
    return v;
}
__device__ __forceinline__ u32 cvt_tf32(float v) {
    u32 t; asm("cvt.rna.tf32.f32 %0, %1;" : "=r"(t) : "f"(v)); return t;
}
__device__ __forceinline__ void mma_tf32(float* c, const u32* a, u32 b0, u32 b1) {
    asm volatile(
        "mma.sync.aligned.m16n8k8.row.col.f32.tf32.tf32.f32 "
        "{%0,%1,%2,%3}, {%4,%5,%6,%7}, {%8,%9}, {%0,%1,%2,%3};"
        : "+f"(c[0]), "+f"(c[1]), "+f"(c[2]), "+f"(c[3])
        : "r"(a[0]), "r"(a[1]), "r"(a[2]), "r"(a[3]), "r"(b0), "r"(b1));
}

// ---------------- tiny prep kernels (proven in R9) ----------------
__global__ void k_styles(const float* __restrict__ wlat,
                         const float* __restrict__ W1, const float* __restrict__ b1,
                         const float* __restrict__ W2, const float* __restrict__ b2,
                         const float* __restrict__ Wv, const float* __restrict__ bv) {
    int b = blockIdx.x, o = threadIdx.x;
    __shared__ float wl[DL];
    for (int d = o; d < DL; d += C) wl[d] = wlat[b*DL + d];
    __syncthreads();
    float a1 = 0.f, a2 = 0.f, av = 0.f;
    const float* w1r = W1 + o*DL;
    const float* w2r = W2 + o*DL;
    const float* wvr = Wv + o*DL;
    #pragma unroll 8
    for (int d = 0; d < DL; d++) {
        float l = wl[d];
        a1 += l * w1r[d];
        a2 += l * w2r[d];
        av += l * wvr[d];
    }
    g_s1[b*C + o] = a1 * C_LIN + b1[o];
    g_s2[b*C + o] = a2 * C_LIN + b2[o];
    g_sv[b*C + o] = av * C_LIN + bv[o];
}

__global__ void k_wsq(const float* __restrict__ cw1, const float* __restrict__ cw2) {
    int o = blockIdx.x, c = threadIdx.x;
    const float* w = (blockIdx.y ? cw2 : cw1) + (o*C + c) * 27;
    float s = 0.f;
    #pragma unroll
    for (int k = 0; k < 27; k++) { float v = w[k]; s += v * v; }
    (blockIdx.y ? g_wsq2 : g_wsq1)[o*C + c] = s;
}

__global__ void k_sig(const float* __restrict__ cwv) {
    int b = blockIdx.x, t = threadIdx.x;
    __shared__ float s1q[C], s2q[C];
    float s1v = g_s1[b*C + t], s2v = g_s2[b*C + t];
    s1q[t] = s1v * s1v;
    s2q[t] = s2v * s2v;
    g_coefv[b*C + t] = g_sv[b*C + t] * SCALEV * cwv[t];
    __syncthreads();
    float a1 = 0.f, a2 = 0.f;
    #pragma unroll 4
    for (int c = 0; c < C; c++) {
        a1 += s1q[c] * g_wsq1[t*C + c];
        a2 += s2q[c] * g_wsq2[t*C + c];
    }
    g_sig1[b*C + t] = rsqrtf(SC2 * a1 + 1e-8f);
    g_sig2[b*C + t] = rsqrtf(SC2 * a2 + 1e-8f);
}

// weight transpose: g_wt[pass][tap][c][o] = tf32_round(cw[(o*C+c)*27 + tap])
__global__ void k_wt(const float* __restrict__ cw1, const float* __restrict__ cw2) {
    int c = blockIdx.x, tap = blockIdx.y, pass = blockIdx.z;
    int o = threadIdx.x;
    const float* src = pass ? cw2 : cw1;
    float v = src[(o*C + c)*27 + tap];
    g_wt[pass][((size_t)tap*C + c)*C + o] = __uint_as_float(cvt_tf32(v));
}

// ---------------- mma.sync tf32 implicit-GEMM conv ----------------
// block = (batch, z-plane z0, 4-y strip y0): D[128 o][128 n], n = x + 32*yi.
// 8 warps: wm = wid>>1 (4 m-groups of 32), wn = wid&1 (2 n-groups of 64).
// 108 iters (4 c-chunks x 27 taps): build A[32k x 128o] + B[32k x 128n] smem
// tiles (stride 136), then 4 k-steps x 16 mma.m16n8k8.tf32 per warp.
template<int PASS>
__global__ void __launch_bounds__(256)
k_convgemm(const float* __restrict__ in, const float* __restrict__ wtp,
           const float* __restrict__ noise, const float* __restrict__ sn,
           const float* __restrict__ bias, float* __restrict__ out) {
    extern __shared__ __align__(16) char smem[];
    const u32 sb = smem_u32(smem);
    const int tid = threadIdx.x;
    const int wid = tid >> 5, lid = tid & 31;
    const int wm = wid >> 1, wn = wid & 1;
    const int b  = blockIdx.z;
    const int z0 = blockIdx.x >> 3;
    const int y0 = (blockIdx.x & 7) * 4;

    float* ms = (float*)(smem + M_OFF);
    const float* style = (PASS == 1) ? g_s1   : g_s2;
    const float* sig   = (PASS == 1) ? g_sig1 : g_sig2;
    if (tid < C) ms[tid] = IN_SCALE * style[b*C + tid];
    __syncthreads();

    float acc[2][8][4];
    #pragma unroll
    for (int mt = 0; mt < 2; mt++)
        #pragma unroll
        for (int nt = 0; nt < 8; nt++)
            #pragma unroll
            for (int r = 0; r < 4; r++) acc[mt][nt][r] = 0.f;

    const float* inb = in + (size_t)b * C * VOL;
    const int xg = tid & 31, gg = tid >> 5;
    const int fr = lid >> 2, fk = lid & 3;     // fragment row / k-within-4

    for (int i = 0; i < 108; i++) {
        const int chunk = i / 27, tap = i % 27;
        const int kz = tap / 9, ky = (tap % 9) / 3, kx = tap % 3;
        const u32 abase = sb + (u32)(i & 1) * BUF_BYTES;
        const u32 bbase = abase + TILE_BYTES;

        // --- build A tile [32 c][128 o] (coalesced LDG.128 -> STS.128) ---
        {
            const float* wsrc = wtp + ((size_t)tap * C + chunk * 32) * C;
            #pragma unroll
            for (int s = 0; s < 4; s++) {
                int a = tid + s * 256;          // 0..1023
                int cc = a >> 5, o4 = (a & 31) * 4;
                float4 w4 = *reinterpret_cast<const float4*>(wsrc + cc * C + o4);
                sts128(abase + (u32)(cc * TSTRIDE + o4) * 4, w4);
            }
        }
        // --- build B tile [32 c][128 n] (shifted, masked, modulated, tf32) ---
        {
            const int zz = z0 + kz - 1;
            const int xx = xg + kx - 1;
            const bool zxok = ((unsigned)zz < 32u) && ((unsigned)xx < 32u);
            #pragma unroll
            for (int t = 0; t < 16; t++) {
                int cc = gg * 4 + (t >> 2);
                int yi = t & 3;
                int yy = y0 + yi + ky - 1;
                float v = 0.f;
                if (zxok && (unsigned)yy < 32u)
                    v = __ldg(inb + (size_t)(chunk * 32 + cc) * VOL
                              + zz * 1024 + yy * 32 + xx) * ms[chunk * 32 + cc];
                sts32(bbase + (u32)(cc * TSTRIDE + yi * 32 + xg) * 4, cvt_tf32(v));
            }
        }
        __syncthreads();

        // --- consume: 4 k-steps x (2 m-tiles x 8 n-tiles) mma ---
        #pragma unroll
        for (int ks = 0; ks < 4; ks++) {
            const int k0 = ks * 8 + fk;
            u32 af[2][4];
            #pragma unroll
            for (int mt = 0; mt < 2; mt++) {
                const int mrow = wm * 32 + mt * 16 + fr;
                af[mt][0] = lds32(abase + (u32)((k0)     * TSTRIDE + mrow)     * 4);
                af[mt][1] = lds32(abase + (u32)((k0)     * TSTRIDE + mrow + 8) * 4);
                af[mt][2] = lds32(abase + (u32)((k0 + 4) * TSTRIDE + mrow)     * 4);
                af[mt][3] = lds32(abase + (u32)((k0 + 4) * TSTRIDE + mrow + 8) * 4);
            }
            #pragma unroll
            for (int nt = 0; nt < 8; nt++) {
                const int ncol = wn * 64 + nt * 8 + fr;
                u32 b0 = lds32(bbase + (u32)((k0)     * TSTRIDE + ncol) * 4);
                u32 b1 = lds32(bbase + (u32)((k0 + 4) * TSTRIDE + ncol) * 4);
                mma_tf32(acc[0][nt], af[0], b0, b1);
                mma_tf32(acc[1][nt], af[1], b0, b1);
            }
        }
    }

    // --- epilogue: demod + noise + bias + leaky relu ---
    const float snv = sn[0];
    const float* nzb = noise + (size_t)b * VOL + z0 * 1024;
    #pragma unroll
    for (int mt = 0; mt < 2; mt++) {
        const int o0 = wm * 32 + mt * 16 + fr;
        const float sg0 = sig[b*C + o0],     bi0 = bias[o0];
        const float sg1 = sig[b*C + o0 + 8], bi1 = bias[o0 + 8];
        float* op0 = out + ((size_t)(b*C + o0))     * VOL + z0 * 1024;
        float* op1 = out + ((size_t)(b*C + o0 + 8)) * VOL + z0 * 1024;
        #pragma unroll
        for (int nt = 0; nt < 8; nt++) {
            const int n0 = wn * 64 + nt * 8 + 2 * fk;
            const int yi = n0 >> 5, x = n0 & 31;
            const int off = (y0 + yi) * 32 + x;
            const float nz0 = nzb[off], nz1 = nzb[off + 1];
            float v;
            v = acc[mt][nt][0] * sg0 + snv * nz0 + bi0; op0[off]     = (v >= 0.f) ? v : 0.2f * v;
            v = acc[mt][nt][1] * sg0 + snv * nz1 + bi0; op0[off + 1] = (v >= 0.f) ? v : 0.2f * v;
            v = acc[mt][nt][2] * sg1 + snv * nz0 + bi1; op1[off]     = (v >= 0.f) ? v : 0.2f * v;
            v = acc[mt][nt][3] * sg1 + snv * nz1 + bi1; op1[off + 1] = (v >= 0.f) ? v : 0.2f * v;
        }
    }
}

// ---------------- to_volume: 1x1x1 conv over channels ----------------
__global__ void k_vol(const float* __restrict__ h2, const float* __restrict__ biasv,
                      float* __restrict__ vol) {
    const int b = blockIdx.y;
    const int p0 = blockIdx.x * 512;
    const int tid = threadIdx.x;
    __shared__ float cf[C];
    if (tid < C) cf[tid] = g_coefv[b*C + tid];
    __syncthreads();
    float a0 = 0.f, a1 = 0.f;
    for (int c = 0; c < C; c++) {
        const float* hp = h2 + ((size_t)(b*C + c)) * VOL + p0;
        const float cv = cf[c];
        a0 += cv * hp[tid];
        a1 += cv * hp[tid + 256];
    }
    const float bv = biasv[0];
    float v0 = a0 + bv, v1 = a1 + bv;
    vol[b*VOL + p0 + tid]       = (v0 >= 0.f) ? v0 : 0.2f * v0;
    vol[b*VOL + p0 + tid + 256] = (v1 >= 0.f) ? v1 : 0.2f * v1;
}

// diagnostic marker
__global__ void k_mark(float* __restrict__ out, int n, float v) {
    for (int i = blockIdx.x * blockDim.x + threadIdx.x; i < n;
         i += gridDim.x * blockDim.x)
        out[i] = v;
}

// ---------------- launch ----------------
extern "C" void kernel_launch(void* const* d_in, const int* in_sizes, int n_in,
                              void* d_out, int out_size) {
    float* out = (float*)d_out;

    static const int sig[18] = {
        33554432, 4096, 262144, 262144,
        65536, 128, 442368, 1, 128,
        65536, 128, 442368, 1, 128,
        65536, 128, 128, 1
    };
    if (n_in != 18) {
        int k = (n_in < 16) ? 1 : (n_in - 15); if (k > 8) k = 8;
        k_mark<<<256, 256>>>(out, out_size, (float)(1 << (2 * k)));
        return;
    }
    for (int i = 0; i < 18; i++) {
        if (in_sizes[i] != sig[i]) {
            k_mark<<<256, 256>>>(out, out_size, 1.0e6f + (float)in_sizes[i]);
            return;
        }
    }

    const float* x      = (const float*)d_in[0];
    const float* wlat   = (const float*)d_in[1];
    const float* noise1 = (const float*)d_in[2];
    const float* noise2 = (const float*)d_in[3];
    const float* W1     = (const float*)d_in[4];
    const float* b1     = (const float*)d_in[5];
    const float* cw1    = (const float*)d_in[6];
    const float* sn1    = (const float*)d_in[7];
    const float* bias1  = (const float*)d_in[8];
    const float* W2     = (const float*)d_in[9];
    const float* b2     = (const float*)d_in[10];
    const float* cw2    = (const float*)d_in[11];
    const float* sn2    = (const float*)d_in[12];
    const float* bias2  = (const float*)d_in[13];
    const float* Wv     = (const float*)d_in[14];
    const float* bv     = (const float*)d_in[15];
    const float* cwv    = (const float*)d_in[16];
    const float* biasv  = (const float*)d_in[17];

    float* h1 = nullptr;
    cudaGetSymbolAddress((void**)&h1, g_h1);
    float* wt = nullptr;
    cudaGetSymbolAddress((void**)&wt, g_wt);

    cudaFuncSetAttribute(k_convgemm<1>, cudaFuncAttributeMaxDynamicSharedMemorySize, CSMEM);
    cudaFuncSetAttribute(k_convgemm<2>, cudaFuncAttributeMaxDynamicSharedMemorySize, CSMEM);

    k_styles<<<BB, C>>>(wlat, W1, b1, W2, b2, Wv, bv);
    k_wsq<<<dim3(C, 2), C>>>(cw1, cw2);
    k_sig<<<BB, C>>>(cwv);
    k_wt<<<dim3(C, 27, 2), C>>>(cw1, cw2);
    k_convgemm<1><<<dim3(256, 1, BB), 256, CSMEM>>>(x,  wt,          noise1, sn1, bias1, h1);
    k_convgemm<2><<<dim3(256, 1, BB), 256, CSMEM>>>(h1, wt + 27*C*C, noise2, sn2, bias2, out);
    if (out_size >= BB*C*VOL + BB*VOL)
        k_vol<<<dim3(64, BB), 256>>>(out, biasv, out + (size_t)BB*C*VOL);
}